// round 10
// baseline (speedup 1.0000x reference)
#include <cuda_runtime.h>

#define NTHR   384
#define NWARP  12
#define KKB    288
#define EPS    1e-6f
#define LAM    1e-3f
#define LN2PI  1.8378770664093453f

// shared-memory float offsets
#define SM_POSE 0                        // 288*32 dup-packed = 9216
#define SM_ACT  (KKB*32)                 // 9216, size 288
#define SM_RED  (SM_ACT + KKB)          // 9504, 33 rows * 385 = 12705 -> ends 22209
#define SM_NMU  (SM_RED + 33*385 + 1)   // 22210 (even), 32*18 = 576
#define SM_AT   (SM_NMU + 576)          // 22786 (even), 512 floats: u64[pp*32+c]
#define SM_BT   (SM_AT + 512)           // 23298, 512
#define SM_AOUT (SM_BT + 512)           // 23810, 32
#define SM_CC2  (SM_AOUT + 32)          // 23842, 32
#define SM_TOTAL (SM_CC2 + 32)          // 23874 floats = 95496 bytes (x2 = 191KB)

// transposed weights: float4 index = n*128 + q*32 + c  (q = row of W_nc)
__device__ float4 g_wt[36864];

__global__ void transpose_w_kernel(const float* __restrict__ w) {
    int j = blockIdx.x * 256 + threadIdx.x;
    if (j < 147456) {
        int n = j >> 9, r = j & 511;
        int q = r >> 7, c = (r >> 2) & 31, e = r & 3;
        ((float*)g_wt)[j] = w[n * 512 + c * 16 + q * 4 + e];
    }
}

// ---------- packed f32x2 primitives ----------
typedef unsigned long long u64;

__device__ __forceinline__ u64 fma2(u64 a, u64 b, u64 c) {
    u64 d; asm("fma.rn.f32x2 %0, %1, %2, %3;" : "=l"(d) : "l"(a), "l"(b), "l"(c));
    return d;
}
__device__ __forceinline__ u64 mul2(u64 a, u64 b) {
    u64 d; asm("mul.rn.f32x2 %0, %1, %2;" : "=l"(d) : "l"(a), "l"(b));
    return d;
}
__device__ __forceinline__ u64 add2(u64 a, u64 b) {
    u64 d; asm("add.rn.f32x2 %0, %1, %2;" : "=l"(d) : "l"(a), "l"(b));
    return d;
}
__device__ __forceinline__ u64 pack2(float lo, float hi) {
    u64 r; asm("mov.b64 %0, {%1, %2};" : "=l"(r) : "f"(lo), "f"(hi)); return r;
}
__device__ __forceinline__ float2 unpack2(u64 v) {
    float2 r; asm("mov.b64 {%0, %1}, %2;" : "=f"(r.x), "=f"(r.y) : "l"(v)); return r;
}

// warp max of a float via integer redux (order-preserving u32 mapping)
__device__ __forceinline__ float redmax32f(float v) {
    int i = __float_as_int(v);
    unsigned u = (unsigned)(i ^ ((i >> 31) | 0x80000000));
    unsigned m;
    asm("redux.sync.max.u32 %0, %1, 0xffffffff;" : "=r"(m) : "r"(u));
    int mi = (int)(m ^ ((~(int)m >> 31) | 0x80000000));
    return __int_as_float(mi);
}
__device__ __forceinline__ float wsum32(float v) {
    #pragma unroll
    for (int d = 16; d; d >>= 1) v += __shfl_xor_sync(0xffffffffu, v, d);
    return v;
}

// v pairs: v2[2i] = (v[4i+0], v[4i+1]), v2[2i+1] = (v[4i+2], v[4i+3])
__device__ __forceinline__ void compute_v2(const float* __restrict__ sm, int n, int c,
                                           u64* __restrict__ v2) {
    const ulonglong2* __restrict__ W = (const ulonglong2*)g_wt + ((size_t)n * 128 + c);
    ulonglong2 w0 = W[0], w1 = W[32], w2 = W[64], w3 = W[96];
    const ulonglong2* __restrict__ P = (const ulonglong2*)(sm + SM_POSE + n * 32);
    #pragma unroll
    for (int i = 0; i < 4; ++i) {
        ulonglong2 pa = P[2 * i];
        ulonglong2 pb = P[2 * i + 1];
        v2[2*i]   = fma2(pa.x, w0.x, fma2(pa.y, w1.x, fma2(pb.x, w2.x, mul2(pb.y, w3.x))));
        v2[2*i+1] = fma2(pa.x, w0.y, fma2(pa.y, w1.y, fma2(pb.x, w2.y, mul2(pb.y, w3.y))));
    }
}

// quadratic-form distance: dist = sum_p A_p v^2 + B_p v  (A,B in transposed SMEM)
__device__ __forceinline__ float dist16ab(const u64* __restrict__ v2,
                                          const float* __restrict__ sm, int c) {
    u64 acc = 0ull;
    #pragma unroll
    for (int pp = 0; pp < 8; ++pp) {
        u64 A = *(const u64*)(sm + SM_AT + 2 * (pp * 32 + c));
        u64 B = *(const u64*)(sm + SM_BT + 2 * (pp * 32 + c));
        acc = fma2(v2[pp], fma2(A, v2[pp], B), acc);
    }
    float2 df = unpack2(acc);
    return df.x + df.y;
}

__device__ __forceinline__ void macc2(float r, const u64* __restrict__ v2,
                                      u64* __restrict__ S1, u64* __restrict__ S2) {
    u64 r2 = pack2(r, r);
    #pragma unroll
    for (int pp = 0; pp < 8; ++pp) {
        u64 rv = mul2(r2, v2[pp]);
        S1[pp] = add2(S1[pp], rv);
        S2[pp] = fma2(rv, v2[pp], S2[pp]);
    }
}

__device__ __forceinline__ void store_red(float* __restrict__ sm, int warp, int c,
                                          const u64* __restrict__ S1,
                                          const u64* __restrict__ S2, float rs) {
    float* base = sm + SM_RED + warp * 32 + c;
    #pragma unroll
    for (int pp = 0; pp < 8; ++pp) {
        float2 a = unpack2(S1[pp]);
        float2 b = unpack2(S2[pp]);
        base[(2*pp)    * 385] = a.x;
        base[(2*pp+1)  * 385] = a.y;
        base[(2*pp+16) * 385] = b.x;
        base[(2*pp+17) * 385] = b.y;
    }
    base[32 * 385] = rs;
}

// parallel finalize on first 256 threads: group g = capsule, lane handles p=2l8,2l8+1
__device__ __forceinline__ void finalize(float* __restrict__ sm, int tid,
                                         const float* __restrict__ gbu,
                                         const float* __restrict__ gba) {
    if (tid >= 256) return;
    const int g = tid >> 3, l8 = tid & 7;
    float rsum = 0.f;
    #pragma unroll
    for (int w = 0; w < NWARP; ++w) rsum += sm[SM_RED + 32 * 385 + w * 32 + g];
    float inv = __fdividef(1.0f, rsum + EPS);
    float nmu[2], isg[2], plog = 0.f, cpart = 0.f;
    #pragma unroll
    for (int t = 0; t < 2; ++t) {
        int p = 2 * l8 + t;
        float s1 = 0.f, s2 = 0.f;
        #pragma unroll
        for (int w = 0; w < NWARP; ++w) {
            s1 += sm[SM_RED + p * 385        + w * 32 + g];
            s2 += sm[SM_RED + (p + 16) * 385 + w * 32 + g];
        }
        float mu = s1 * inv;
        float sg = (s2 - 2.f * mu * s1 + mu * mu * rsum) * inv + EPS;
        sm[SM_NMU + g * 18 + p] = -mu;
        nmu[t] = -mu;
        isg[t] = __fdividef(0.5f, sg);
        plog  += __logf(sg);
        cpart  = fmaf(isg[t] * nmu[t], nmu[t], cpart);
    }
    *(u64*)(sm + SM_AT + 2 * (l8 * 32 + g)) = pack2(isg[0], isg[1]);
    *(u64*)(sm + SM_BT + 2 * (l8 * 32 + g)) =
        pack2(2.f * isg[0] * nmu[0], 2.f * isg[1] * nmu[1]);
    #pragma unroll
    for (int d = 1; d < 8; d <<= 1) {
        plog  += __shfl_xor_sync(0xffffffffu, plog, d);
        cpart += __shfl_xor_sync(0xffffffffu, cpart, d);
    }
    if (l8 == 0) {
        float cost = rsum * (16.f * gbu[g] + 0.5f * plog);
        float ao = __fdividef(1.f, 1.f + __expf(LAM * (cost - gba[g])));
        sm[SM_AOUT + g] = ao;
        sm[SM_CC2 + g]  = __logf(ao) - 0.5f * plog - 8.f * LN2PI - cpart;
    }
}

__global__ void __launch_bounds__(NTHR, 2)
convcaps_kernel(const float* __restrict__ gx, const float* __restrict__ ga,
                const float* __restrict__ gbu, const float* __restrict__ gba,
                float* __restrict__ gout)
{
    extern __shared__ float sm[];
    const int tid  = threadIdx.x;
    const int warp = tid >> 5;             // 0..11
    const int c    = tid & 31;
    const int blk  = blockIdx.x;           // b*36 + h*6 + w
    const int b    = blk / 36;
    const int hw   = blk - b * 36;
    const int h2   = (hw / 6) * 2;
    const int w2   = (hw % 6) * 2;

    // ---- load pose patch duplicated: row n = [p0,p0,p1,p1,...,p15,p15] ----
    for (int idx = tid; idx < KKB * 16; idx += NTHR) {
        int n = idx >> 4, q = idx & 15;
        int ki = n / 96; int rem = n - ki * 96;
        int kj = rem >> 5; int bi = rem & 31;
        float f = gx[(size_t)((b * 14 + h2 + ki) * 14 + (w2 + kj)) * 512 + bi * 16 + q];
        *(float2*)(sm + SM_POSE + n * 32 + 2 * q) = make_float2(f, f);
    }
    for (int n = tid; n < KKB; n += NTHR) {
        int ki = n / 96; int rem = n - ki * 96;
        int kj = rem >> 5; int bi = rem & 31;
        sm[SM_ACT + n] = ga[((b * 14 + h2 + ki) * 14 + (w2 + kj)) * 32 + bi];
    }
    __syncthreads();

    u64 S1[8], S2[8];
    float rs;

    // ================= pass 0: M-step with uniform r = act/32 =================
    #pragma unroll
    for (int pp = 0; pp < 8; ++pp) { S1[pp] = 0ull; S2[pp] = 0ull; }
    rs = 0.f;
    for (int i = 0; i < 24; ++i) {
        int n = warp + NWARP * i;
        u64 v2[8];
        compute_v2(sm, n, c, v2);
        float r = sm[SM_ACT + n] * (1.0f / 32.0f);
        rs += r;
        macc2(r, v2, S1, S2);
    }
    store_red(sm, warp, c, S1, S2, rs);
    __syncthreads();
    finalize(sm, tid, gbu, gba);
    __syncthreads();

    // ================= 2 fused E+M passes =================
    for (int it = 0; it < 2; ++it) {
        const float ccst2 = sm[SM_CC2 + c];
        #pragma unroll
        for (int pp = 0; pp < 8; ++pp) { S1[pp] = 0ull; S2[pp] = 0ull; }
        rs = 0.f;

        for (int i = 0; i < 24; ++i) {
            int n = warp + NWARP * i;
            u64 v2[8];
            compute_v2(sm, n, c, v2);
            float l = ccst2 - dist16ab(v2, sm, c);
            float m = redmax32f(l);
            float e = __expf(l - m);
            float s = wsum32(e);
            float r = __fdividef(e, s);
            rs += r;
            macc2(r, v2, S1, S2);
        }
        store_red(sm, warp, c, S1, S2, rs);
        __syncthreads();
        finalize(sm, tid, gbu, gba);
        __syncthreads();
    }

    // ---- outputs: p_out (288*512 floats) then a_out (288*32 floats) ----
    for (int idx = tid; idx < 512; idx += NTHR) {
        int co = idx >> 4, p = idx & 15;
        gout[(size_t)blk * 512 + idx] = -sm[SM_NMU + co * 18 + p];
    }
    if (tid < 32)
        gout[147456 + blk * 32 + tid] = sm[SM_AOUT + tid];
}

extern "C" void kernel_launch(void* const* d_in, const int* in_sizes, int n_in,
                              void* d_out, int out_size) {
    const float* x  = (const float*)d_in[0];
    const float* a  = (const float*)d_in[1];
    const float* w  = (const float*)d_in[2];
    const float* bu = (const float*)d_in[3];
    const float* ba = (const float*)d_in[4];
    float* out = (float*)d_out;
    (void)in_sizes; (void)n_in; (void)out_size;

    transpose_w_kernel<<<576, 256>>>(w);

    const int smem_bytes = SM_TOTAL * (int)sizeof(float);  // 95496 B
    cudaFuncSetAttribute(convcaps_kernel,
                         cudaFuncAttributeMaxDynamicSharedMemorySize, smem_bytes);
    convcaps_kernel<<<288, NTHR, smem_bytes>>>(x, a, bu, ba, out);
}

// round 11
// speedup vs baseline: 1.5824x; 1.5824x over previous
#include <cuda_runtime.h>

#define NTHR   256
#define KKB    288
#define EPS    1e-6f
#define LAM    1e-3f
#define LN2PI  1.8378770664093453f

// shared-memory float offsets
#define SM_POSE 0                       // 288*32 dup-packed = 9216
#define SM_ACT  (KKB*32)                // 9216, size 288
#define SM_RED  (SM_ACT + KKB)         // 9504, 33*257 = 8481 -> ends 17985
#define SM_NMU  (SM_RED + 33*257 + 1)  // 17986 (even), 32*18 = 576
#define SM_AT   (SM_NMU + 576)         // 18562 (8B-aligned), 512 floats: u64[pp*32+c]
#define SM_BT   (SM_AT + 512)          // 19074, 512 floats
#define SM_AOUT (SM_BT + 512)          // 19586, 32
#define SM_CC2  (SM_AOUT + 32)         // 19618, 32
#define SM_TOTAL (SM_CC2 + 32)         // 19650 floats = 78600 bytes

// transposed weights: float4 index = n*128 + q*32 + c  (q = row of W_nc)
__device__ float4 g_wt[36864];

__global__ void transpose_w_kernel(const float* __restrict__ w) {
    int j = blockIdx.x * 256 + threadIdx.x;
    if (j < 147456) {
        int n = j >> 9, r = j & 511;
        int q = r >> 7, c = (r >> 2) & 31, e = r & 3;
        ((float*)g_wt)[j] = w[n * 512 + c * 16 + q * 4 + e];
    }
}

// ---------- packed f32x2 primitives ----------
typedef unsigned long long u64;

__device__ __forceinline__ u64 fma2(u64 a, u64 b, u64 c) {
    u64 d; asm("fma.rn.f32x2 %0, %1, %2, %3;" : "=l"(d) : "l"(a), "l"(b), "l"(c));
    return d;
}
__device__ __forceinline__ u64 mul2(u64 a, u64 b) {
    u64 d; asm("mul.rn.f32x2 %0, %1, %2;" : "=l"(d) : "l"(a), "l"(b));
    return d;
}
__device__ __forceinline__ u64 add2(u64 a, u64 b) {
    u64 d; asm("add.rn.f32x2 %0, %1, %2;" : "=l"(d) : "l"(a), "l"(b));
    return d;
}
__device__ __forceinline__ u64 pack2(float lo, float hi) {
    u64 r; asm("mov.b64 %0, {%1, %2};" : "=l"(r) : "f"(lo), "f"(hi)); return r;
}
__device__ __forceinline__ float2 unpack2(u64 v) {
    float2 r; asm("mov.b64 {%0, %1}, %2;" : "=f"(r.x), "=f"(r.y) : "l"(v)); return r;
}

// warp max of a float via integer redux (order-preserving u32 mapping)
__device__ __forceinline__ float redmax32f(float v) {
    int i = __float_as_int(v);
    unsigned u = (unsigned)(i ^ ((i >> 31) | 0x80000000));
    unsigned m;
    asm("redux.sync.max.u32 %0, %1, 0xffffffff;" : "=r"(m) : "r"(u));
    int mi = (int)(m ^ ((~(int)m >> 31) | 0x80000000));
    return __int_as_float(mi);
}

// warp sum of e in [0,1] via fixed-point redux (scale 2^23; max sum 2^28, no overflow)
__device__ __forceinline__ float redsum01(float e) {
    unsigned q = (unsigned)__float2uint_rn(e * 8388608.f);
    unsigned t;
    asm("redux.sync.add.u32 %0, %1, 0xffffffff;" : "=r"(t) : "r"(q));
    return (float)t * (1.0f / 8388608.f);
}

// v pairs: v2[2i] = (v[4i+0], v[4i+1]), v2[2i+1] = (v[4i+2], v[4i+3])
__device__ __forceinline__ void compute_v2(const float* __restrict__ sm, int n, int c,
                                           u64* __restrict__ v2) {
    const ulonglong2* __restrict__ W = (const ulonglong2*)g_wt + ((size_t)n * 128 + c);
    ulonglong2 w0 = W[0], w1 = W[32], w2 = W[64], w3 = W[96];
    const ulonglong2* __restrict__ P = (const ulonglong2*)(sm + SM_POSE + n * 32);
    #pragma unroll
    for (int i = 0; i < 4; ++i) {
        ulonglong2 pa = P[2 * i];
        ulonglong2 pb = P[2 * i + 1];
        v2[2*i]   = fma2(pa.x, w0.x, fma2(pa.y, w1.x, fma2(pb.x, w2.x, mul2(pb.y, w3.x))));
        v2[2*i+1] = fma2(pa.x, w0.y, fma2(pa.y, w1.y, fma2(pb.x, w2.y, mul2(pb.y, w3.y))));
    }
}

// quadratic-form distance: dist = sum_p A_p v^2 + B_p v  (A,B in transposed SMEM)
__device__ __forceinline__ float dist16ab(const u64* __restrict__ v2,
                                          const float* __restrict__ sm, int c) {
    u64 acc = 0ull;
    #pragma unroll
    for (int pp = 0; pp < 8; ++pp) {
        u64 A = *(const u64*)(sm + SM_AT + 2 * (pp * 32 + c));
        u64 B = *(const u64*)(sm + SM_BT + 2 * (pp * 32 + c));
        acc = fma2(v2[pp], fma2(A, v2[pp], B), acc);
    }
    float2 df = unpack2(acc);
    return df.x + df.y;
}

__device__ __forceinline__ void macc2(float r, const u64* __restrict__ v2,
                                      u64* __restrict__ S1, u64* __restrict__ S2) {
    u64 r2 = pack2(r, r);
    #pragma unroll
    for (int pp = 0; pp < 8; ++pp) {
        u64 rv = mul2(r2, v2[pp]);
        S1[pp] = add2(S1[pp], rv);
        S2[pp] = fma2(rv, v2[pp], S2[pp]);
    }
}

__device__ __forceinline__ void store_red(float* __restrict__ sm, int warp, int c,
                                          const u64* __restrict__ S1,
                                          const u64* __restrict__ S2, float rs) {
    float* base = sm + SM_RED + warp * 32 + c;
    #pragma unroll
    for (int pp = 0; pp < 8; ++pp) {
        float2 a = unpack2(S1[pp]);
        float2 b = unpack2(S2[pp]);
        base[(2*pp)    * 257] = a.x;
        base[(2*pp+1)  * 257] = a.y;
        base[(2*pp+16) * 257] = b.x;
        base[(2*pp+17) * 257] = b.y;
    }
    base[32 * 257] = rs;
}

// parallel finalize: 32 groups of 8 lanes; group g = capsule c, lane handles p=2l8,2l8+1
// Produces: SM_NMU (output), SM_AT = isig pairs, SM_BT = 2*isig*nmu pairs,
//           SM_CC2 = ln(a_out) - 0.5*sumlog - 8*ln(2pi) - sum_p isig*mu^2
__device__ __forceinline__ void finalize(float* __restrict__ sm, int tid,
                                         const float* __restrict__ gbu,
                                         const float* __restrict__ gba) {
    const int g = tid >> 3, l8 = tid & 7;
    float rsum = 0.f;
    #pragma unroll
    for (int w = 0; w < 8; ++w) rsum += sm[SM_RED + 32 * 257 + w * 32 + g];
    float inv = __fdividef(1.0f, rsum + EPS);
    float nmu[2], isg[2], plog = 0.f, cpart = 0.f;
    #pragma unroll
    for (int t = 0; t < 2; ++t) {
        int p = 2 * l8 + t;
        float s1 = 0.f, s2 = 0.f;
        #pragma unroll
        for (int w = 0; w < 8; ++w) {
            s1 += sm[SM_RED + p * 257        + w * 32 + g];
            s2 += sm[SM_RED + (p + 16) * 257 + w * 32 + g];
        }
        float mu = s1 * inv;
        float sg = (s2 - 2.f * mu * s1 + mu * mu * rsum) * inv + EPS;
        sm[SM_NMU + g * 18 + p] = -mu;
        nmu[t] = -mu;
        isg[t] = __fdividef(0.5f, sg);
        plog  += __logf(sg);
        cpart  = fmaf(isg[t] * nmu[t], nmu[t], cpart);
    }
    *(u64*)(sm + SM_AT + 2 * (l8 * 32 + g)) = pack2(isg[0], isg[1]);
    *(u64*)(sm + SM_BT + 2 * (l8 * 32 + g)) =
        pack2(2.f * isg[0] * nmu[0], 2.f * isg[1] * nmu[1]);
    #pragma unroll
    for (int d = 1; d < 8; d <<= 1) {
        plog  += __shfl_xor_sync(0xffffffffu, plog, d);
        cpart += __shfl_xor_sync(0xffffffffu, cpart, d);
    }
    if (l8 == 0) {
        float cost = rsum * (16.f * gbu[g] + 0.5f * plog);
        float ao = __fdividef(1.f, 1.f + __expf(LAM * (cost - gba[g])));
        sm[SM_AOUT + g] = ao;
        sm[SM_CC2 + g]  = __logf(ao) - 0.5f * plog - 8.f * LN2PI - cpart;
    }
}

__global__ void __launch_bounds__(NTHR, 2)
convcaps_kernel(const float* __restrict__ gx, const float* __restrict__ ga,
                const float* __restrict__ gbu, const float* __restrict__ gba,
                float* __restrict__ gout)
{
    extern __shared__ float sm[];
    const int tid  = threadIdx.x;
    const int warp = tid >> 5;
    const int c    = tid & 31;
    const int blk  = blockIdx.x;           // b*36 + h*6 + w
    const int b    = blk / 36;
    const int hw   = blk - b * 36;
    const int h2   = (hw / 6) * 2;
    const int w2   = (hw % 6) * 2;

    // ---- load pose patch duplicated: row n = [p0,p0,p1,p1,...,p15,p15] ----
    for (int idx = tid; idx < KKB * 16; idx += NTHR) {
        int n = idx >> 4, q = idx & 15;
        int ki = n / 96; int rem = n - ki * 96;
        int kj = rem >> 5; int bi = rem & 31;
        float f = gx[(size_t)((b * 14 + h2 + ki) * 14 + (w2 + kj)) * 512 + bi * 16 + q];
        *(float2*)(sm + SM_POSE + n * 32 + 2 * q) = make_float2(f, f);
    }
    for (int n = tid; n < KKB; n += NTHR) {
        int ki = n / 96; int rem = n - ki * 96;
        int kj = rem >> 5; int bi = rem & 31;
        sm[SM_ACT + n] = ga[((b * 14 + h2 + ki) * 14 + (w2 + kj)) * 32 + bi];
    }
    __syncthreads();

    u64 S1[8], S2[8];
    float rs;

    // ================= pass 0: M-step with uniform r = act/32 =================
    #pragma unroll
    for (int pp = 0; pp < 8; ++pp) { S1[pp] = 0ull; S2[pp] = 0ull; }
    rs = 0.f;
    for (int i = 0; i < 36; i += 2) {
        int n0 = warp + 8 * i, n1 = n0 + 8;
        u64 va[8], vb[8];
        compute_v2(sm, n0, c, va);
        compute_v2(sm, n1, c, vb);
        float r0 = sm[SM_ACT + n0] * (1.0f / 32.0f);
        float r1 = sm[SM_ACT + n1] * (1.0f / 32.0f);
        rs += r0 + r1;
        macc2(r0, va, S1, S2);
        macc2(r1, vb, S1, S2);
    }
    store_red(sm, warp, c, S1, S2, rs);
    __syncthreads();
    finalize(sm, tid, gbu, gba);
    __syncthreads();

    // ================= 2 fused E+M passes (2-way interleaved) =================
    for (int it = 0; it < 2; ++it) {
        const float ccst2 = sm[SM_CC2 + c];
        #pragma unroll
        for (int pp = 0; pp < 8; ++pp) { S1[pp] = 0ull; S2[pp] = 0ull; }
        rs = 0.f;

        for (int i = 0; i < 36; i += 2) {
            int n0 = warp + 8 * i, n1 = n0 + 8;
            u64 va[8], vb[8];
            compute_v2(sm, n0, c, va);
            compute_v2(sm, n1, c, vb);
            float l0 = ccst2 - dist16ab(va, sm, c);
            float l1 = ccst2 - dist16ab(vb, sm, c);
            float m0 = redmax32f(l0);
            float m1 = redmax32f(l1);
            float e0 = __expf(l0 - m0);
            float e1 = __expf(l1 - m1);
            float s0 = redsum01(e0);
            float s1 = redsum01(e1);
            float r0 = __fdividef(e0, s0);
            float r1 = __fdividef(e1, s1);
            rs += r0 + r1;
            macc2(r0, va, S1, S2);
            macc2(r1, vb, S1, S2);
        }
        store_red(sm, warp, c, S1, S2, rs);
        __syncthreads();
        finalize(sm, tid, gbu, gba);
        __syncthreads();
    }

    // ---- outputs: p_out (288*512 floats) then a_out (288*32 floats) ----
    for (int idx = tid; idx < 512; idx += NTHR) {
        int co = idx >> 4, p = idx & 15;
        gout[(size_t)blk * 512 + idx] = -sm[SM_NMU + co * 18 + p];
    }
    if (tid < 32)
        gout[147456 + blk * 32 + tid] = sm[SM_AOUT + tid];
}

extern "C" void kernel_launch(void* const* d_in, const int* in_sizes, int n_in,
                              void* d_out, int out_size) {
    const float* x  = (const float*)d_in[0];
    const float* a  = (const float*)d_in[1];
    const float* w  = (const float*)d_in[2];
    const float* bu = (const float*)d_in[3];
    const float* ba = (const float*)d_in[4];
    float* out = (float*)d_out;
    (void)in_sizes; (void)n_in; (void)out_size;

    transpose_w_kernel<<<576, 256>>>(w);

    const int smem_bytes = SM_TOTAL * (int)sizeof(float);  // 78600 B
    cudaFuncSetAttribute(convcaps_kernel,
                         cudaFuncAttributeMaxDynamicSharedMemorySize, smem_bytes);
    convcaps_kernel<<<288, NTHR, smem_bytes>>>(x, a, bu, ba, out);
}

// round 12
// speedup vs baseline: 1.5955x; 1.0083x over previous
#include <cuda_runtime.h>

#define NTHR   256
#define KKB    288
#define EPS    1e-6f
#define LAM    1e-3f
#define LN2PI  1.8378770664093453f
#define LOG2E  1.4426950408889634f

// shared-memory float offsets
#define SM_POSE 0                       // 288*32 dup-packed = 9216
#define SM_ACT  (KKB*32)                // 9216, size 288
#define SM_RED  (SM_ACT + KKB)         // 9504, 33*257 = 8481 -> ends 17985
#define SM_NMU  (SM_RED + 33*257 + 1)  // 17986 (even), 32*18 = 576
#define SM_ABT  (SM_NMU + 576)         // 18562... need 16B alignment -> pad to 18564
#define SM_ABT16 ((SM_ABT + 3) & ~3)   // 18564 (16B-aligned), 1024 floats: [pp][c]{A2,B2}
#define SM_AOUT (SM_ABT16 + 1024)      // 19588, 32
#define SM_CC2  (SM_AOUT + 32)         // 19620, 32
#define SM_TOTAL (SM_CC2 + 32)         // 19652 floats = 78608 bytes

// transposed weights: float4 index = n*128 + q*32 + c  (q = row of W_nc)
__device__ float4 g_wt[36864];

__global__ void transpose_w_kernel(const float* __restrict__ w) {
    int j = blockIdx.x * 256 + threadIdx.x;
    if (j < 147456) {
        int n = j >> 9, r = j & 511;
        int q = r >> 7, c = (r >> 2) & 31, e = r & 3;
        ((float*)g_wt)[j] = w[n * 512 + c * 16 + q * 4 + e];
    }
}

// ---------- packed f32x2 primitives ----------
typedef unsigned long long u64;

__device__ __forceinline__ u64 fma2(u64 a, u64 b, u64 c) {
    u64 d; asm("fma.rn.f32x2 %0, %1, %2, %3;" : "=l"(d) : "l"(a), "l"(b), "l"(c));
    return d;
}
__device__ __forceinline__ u64 mul2(u64 a, u64 b) {
    u64 d; asm("mul.rn.f32x2 %0, %1, %2;" : "=l"(d) : "l"(a), "l"(b));
    return d;
}
__device__ __forceinline__ u64 add2(u64 a, u64 b) {
    u64 d; asm("add.rn.f32x2 %0, %1, %2;" : "=l"(d) : "l"(a), "l"(b));
    return d;
}
__device__ __forceinline__ u64 pack2(float lo, float hi) {
    u64 r; asm("mov.b64 %0, {%1, %2};" : "=l"(r) : "f"(lo), "f"(hi)); return r;
}
__device__ __forceinline__ float2 unpack2(u64 v) {
    float2 r; asm("mov.b64 {%0, %1}, %2;" : "=f"(r.x), "=f"(r.y) : "l"(v)); return r;
}

// warp max of a float via integer redux (order-preserving u32 mapping)
__device__ __forceinline__ float redmax32f(float v) {
    int i = __float_as_int(v);
    unsigned u = (unsigned)(i ^ ((i >> 31) | 0x80000000));
    unsigned m;
    asm("redux.sync.max.u32 %0, %1, 0xffffffff;" : "=r"(m) : "r"(u));
    int mi = (int)(m ^ ((~(int)m >> 31) | 0x80000000));
    return __int_as_float(mi);
}

// warp sum of e in [0,1] via fixed-point redux (scale 2^23; max sum 2^28, no overflow)
__device__ __forceinline__ float redsum01(float e) {
    unsigned q = (unsigned)__float2uint_rn(e * 8388608.f);
    unsigned t;
    asm("redux.sync.add.u32 %0, %1, 0xffffffff;" : "=r"(t) : "r"(q));
    return (float)t * (1.0f / 8388608.f);
}

// v pairs: v2[2i] = (v[4i+0], v[4i+1]), v2[2i+1] = (v[4i+2], v[4i+3])
__device__ __forceinline__ void compute_v2(const float* __restrict__ sm, int n, int c,
                                           u64* __restrict__ v2) {
    const ulonglong2* __restrict__ W = (const ulonglong2*)g_wt + ((size_t)n * 128 + c);
    ulonglong2 w0 = W[0], w1 = W[32], w2 = W[64], w3 = W[96];
    const ulonglong2* __restrict__ P = (const ulonglong2*)(sm + SM_POSE + n * 32);
    #pragma unroll
    for (int i = 0; i < 4; ++i) {
        ulonglong2 pa = P[2 * i];
        ulonglong2 pb = P[2 * i + 1];
        v2[2*i]   = fma2(pa.x, w0.x, fma2(pa.y, w1.x, fma2(pb.x, w2.x, mul2(pb.y, w3.x))));
        v2[2*i+1] = fma2(pa.x, w0.y, fma2(pa.y, w1.y, fma2(pb.x, w2.y, mul2(pb.y, w3.y))));
    }
}

// paired quadratic-form distance (log2 domain): A,B loaded ONCE, used for both chains
__device__ __forceinline__ void dist_pair(const u64* __restrict__ va,
                                          const u64* __restrict__ vb,
                                          const float* __restrict__ sm, int c,
                                          float& d0, float& d1) {
    u64 acc0 = 0ull, acc1 = 0ull;
    #pragma unroll
    for (int pp = 0; pp < 8; ++pp) {
        ulonglong2 ab = *(const ulonglong2*)(sm + SM_ABT16 + 4 * (pp * 32 + c));
        acc0 = fma2(va[pp], fma2(ab.x, va[pp], ab.y), acc0);
        acc1 = fma2(vb[pp], fma2(ab.x, vb[pp], ab.y), acc1);
    }
    float2 f0 = unpack2(acc0), f1 = unpack2(acc1);
    d0 = f0.x + f0.y;
    d1 = f1.x + f1.y;
}

__device__ __forceinline__ void macc2(float r, const u64* __restrict__ v2,
                                      u64* __restrict__ S1, u64* __restrict__ S2) {
    u64 r2 = pack2(r, r);
    #pragma unroll
    for (int pp = 0; pp < 8; ++pp) {
        u64 rv = mul2(r2, v2[pp]);
        S1[pp] = add2(S1[pp], rv);
        S2[pp] = fma2(rv, v2[pp], S2[pp]);
    }
}

__device__ __forceinline__ void store_red(float* __restrict__ sm, int warp, int c,
                                          const u64* __restrict__ S1,
                                          const u64* __restrict__ S2, float rs) {
    float* base = sm + SM_RED + warp * 32 + c;
    #pragma unroll
    for (int pp = 0; pp < 8; ++pp) {
        float2 a = unpack2(S1[pp]);
        float2 b = unpack2(S2[pp]);
        base[(2*pp)    * 257] = a.x;
        base[(2*pp+1)  * 257] = a.y;
        base[(2*pp+16) * 257] = b.x;
        base[(2*pp+17) * 257] = b.y;
    }
    base[32 * 257] = rs;
}

// parallel finalize: 32 groups of 8 lanes; group g = capsule c, lane handles p=2l8,2l8+1
// Produces: SM_NMU (output), SM_ABT16 = {A-pair, B-pair} (log2 domain),
//           SM_CC2 = log2e*(ln(a_out) - 0.5*sumlog - 8*ln(2pi) - sum_p isig*mu^2)
__device__ __forceinline__ void finalize(float* __restrict__ sm, int tid,
                                         const float* __restrict__ gbu,
                                         const float* __restrict__ gba) {
    const int g = tid >> 3, l8 = tid & 7;
    float rsum = 0.f;
    #pragma unroll
    for (int w = 0; w < 8; ++w) rsum += sm[SM_RED + 32 * 257 + w * 32 + g];
    float inv = __fdividef(1.0f, rsum + EPS);
    float nmu[2], isg[2], plog = 0.f, cpart = 0.f;
    #pragma unroll
    for (int t = 0; t < 2; ++t) {
        int p = 2 * l8 + t;
        float s1 = 0.f, s2 = 0.f;
        #pragma unroll
        for (int w = 0; w < 8; ++w) {
            s1 += sm[SM_RED + p * 257        + w * 32 + g];
            s2 += sm[SM_RED + (p + 16) * 257 + w * 32 + g];
        }
        float mu = s1 * inv;
        float sg = (s2 - 2.f * mu * s1 + mu * mu * rsum) * inv + EPS;
        sm[SM_NMU + g * 18 + p] = -mu;
        nmu[t] = -mu;
        isg[t] = __fdividef(0.5f, sg);
        plog  += __logf(sg);
        cpart  = fmaf(isg[t] * nmu[t], nmu[t], cpart);
    }
    {
        ulonglong2 ab;
        ab.x = pack2(isg[0] * LOG2E, isg[1] * LOG2E);
        ab.y = pack2(2.f * isg[0] * nmu[0] * LOG2E, 2.f * isg[1] * nmu[1] * LOG2E);
        *(ulonglong2*)(sm + SM_ABT16 + 4 * (l8 * 32 + g)) = ab;
    }
    #pragma unroll
    for (int d = 1; d < 8; d <<= 1) {
        plog  += __shfl_xor_sync(0xffffffffu, plog, d);
        cpart += __shfl_xor_sync(0xffffffffu, cpart, d);
    }
    if (l8 == 0) {
        float cost = rsum * (16.f * gbu[g] + 0.5f * plog);
        float ao = __fdividef(1.f, 1.f + __expf(LAM * (cost - gba[g])));
        sm[SM_AOUT + g] = ao;
        sm[SM_CC2 + g]  = LOG2E * (__logf(ao) - 0.5f * plog - 8.f * LN2PI - cpart);
    }
}

__global__ void __launch_bounds__(NTHR, 2)
convcaps_kernel(const float* __restrict__ gx, const float* __restrict__ ga,
                const float* __restrict__ gbu, const float* __restrict__ gba,
                float* __restrict__ gout)
{
    extern __shared__ float sm[];
    const int tid  = threadIdx.x;
    const int warp = tid >> 5;
    const int c    = tid & 31;
    const int blk  = blockIdx.x;           // b*36 + h*6 + w
    const int b    = blk / 36;
    const int hw   = blk - b * 36;
    const int h2   = (hw / 6) * 2;
    const int w2   = (hw % 6) * 2;

    // ---- load pose patch duplicated: row n = [p0,p0,p1,p1,...,p15,p15] ----
    for (int idx = tid; idx < KKB * 16; idx += NTHR) {
        int n = idx >> 4, q = idx & 15;
        int ki = n / 96; int rem = n - ki * 96;
        int kj = rem >> 5; int bi = rem & 31;
        float f = gx[(size_t)((b * 14 + h2 + ki) * 14 + (w2 + kj)) * 512 + bi * 16 + q];
        *(float2*)(sm + SM_POSE + n * 32 + 2 * q) = make_float2(f, f);
    }
    for (int n = tid; n < KKB; n += NTHR) {
        int ki = n / 96; int rem = n - ki * 96;
        int kj = rem >> 5; int bi = rem & 31;
        sm[SM_ACT + n] = ga[((b * 14 + h2 + ki) * 14 + (w2 + kj)) * 32 + bi];
    }
    __syncthreads();

    u64 S1[8], S2[8];
    float rs;

    // ================= pass 0: M-step with uniform r = act/32 =================
    #pragma unroll
    for (int pp = 0; pp < 8; ++pp) { S1[pp] = 0ull; S2[pp] = 0ull; }
    rs = 0.f;
    for (int i = 0; i < 36; i += 2) {
        int n0 = warp + 8 * i, n1 = n0 + 8;
        u64 va[8], vb[8];
        compute_v2(sm, n0, c, va);
        compute_v2(sm, n1, c, vb);
        float r0 = sm[SM_ACT + n0] * (1.0f / 32.0f);
        float r1 = sm[SM_ACT + n1] * (1.0f / 32.0f);
        rs += r0 + r1;
        macc2(r0, va, S1, S2);
        macc2(r1, vb, S1, S2);
    }
    store_red(sm, warp, c, S1, S2, rs);
    __syncthreads();
    finalize(sm, tid, gbu, gba);
    __syncthreads();

    // ================= 2 fused E+M passes (2-way interleaved, shared A/B) =======
    for (int it = 0; it < 2; ++it) {
        const float ccst2 = sm[SM_CC2 + c];
        #pragma unroll
        for (int pp = 0; pp < 8; ++pp) { S1[pp] = 0ull; S2[pp] = 0ull; }
        rs = 0.f;

        for (int i = 0; i < 36; i += 2) {
            int n0 = warp + 8 * i, n1 = n0 + 8;
            u64 va[8], vb[8];
            compute_v2(sm, n0, c, va);
            compute_v2(sm, n1, c, vb);
            float d0, d1;
            dist_pair(va, vb, sm, c, d0, d1);
            float l0 = ccst2 - d0;                 // log2 domain
            float l1 = ccst2 - d1;
            float m0 = redmax32f(l0);
            float m1 = redmax32f(l1);
            float e0 = exp2f(l0 - m0);
            float e1 = exp2f(l1 - m1);
            float s0 = redsum01(e0);
            float s1 = redsum01(e1);
            float r0 = __fdividef(e0, s0);
            float r1 = __fdividef(e1, s1);
            rs += r0 + r1;
            macc2(r0, va, S1, S2);
            macc2(r1, vb, S1, S2);
        }
        store_red(sm, warp, c, S1, S2, rs);
        __syncthreads();
        finalize(sm, tid, gbu, gba);
        __syncthreads();
    }

    // ---- outputs: p_out (288*512 floats) then a_out (288*32 floats) ----
    for (int idx = tid; idx < 512; idx += NTHR) {
        int co = idx >> 4, p = idx & 15;
        gout[(size_t)blk * 512 + idx] = -sm[SM_NMU + co * 18 + p];
    }
    if (tid < 32)
        gout[147456 + blk * 32 + tid] = sm[SM_AOUT + tid];
}

extern "C" void kernel_launch(void* const* d_in, const int* in_sizes, int n_in,
                              void* d_out, int out_size) {
    const float* x  = (const float*)d_in[0];
    const float* a  = (const float*)d_in[1];
    const float* w  = (const float*)d_in[2];
    const float* bu = (const float*)d_in[3];
    const float* ba = (const float*)d_in[4];
    float* out = (float*)d_out;
    (void)in_sizes; (void)n_in; (void)out_size;

    transpose_w_kernel<<<576, 256>>>(w);

    const int smem_bytes = SM_TOTAL * (int)sizeof(float);  // 78608 B
    cudaFuncSetAttribute(convcaps_kernel,
                         cudaFuncAttributeMaxDynamicSharedMemorySize, smem_bytes);
    convcaps_kernel<<<288, NTHR, smem_bytes>>>(x, a, bu, ba, out);
}